// round 12
// baseline (speedup 1.0000x reference)
#include <cuda_runtime.h>
#include <cuda_fp16.h>
#include <cstdint>

#define Bc 4
#define Tc 2048
#define Cc 1024
#define NH 16
#define HD 64

// Scratch (alloc-free rule: __device__ globals). All fp16.
__device__ __half g_x[(size_t)Bc * Tc * Cc];               // fp16 x
__device__ __half g_qkv[(size_t)3 * Bc * NH * Tc * HD];    // [3][B][H][T][HD]; Q pre-scaled by 0.125
__device__ __half g_y[(size_t)Bc * Tc * Cc];               // [B][T][C]
__device__ __half g_wT[(size_t)(3 * Cc + Cc) * Cc];        // w_attn^T then w_proj^T, [N][K]

// ---------------------------------------------------------------------------
// Helpers
// ---------------------------------------------------------------------------
__device__ __forceinline__ uint32_t smem_u32(const void* p) {
    uint32_t a;
    asm("{ .reg .u64 t; cvta.to.shared.u64 t, %1; cvt.u32.u64 %0, t; }"
        : "=r"(a) : "l"(p));
    return a;
}
// m16n8k16 fp16 mma, fp32 accum.
__device__ __forceinline__ void mma16(float* d, const uint32_t* a, uint32_t b0, uint32_t b1) {
    asm volatile(
        "mma.sync.aligned.m16n8k16.row.col.f32.f16.f16.f32 "
        "{%0,%1,%2,%3}, {%4,%5,%6,%7}, {%8,%9}, {%0,%1,%2,%3};"
        : "+f"(d[0]), "+f"(d[1]), "+f"(d[2]), "+f"(d[3])
        : "r"(a[0]), "r"(a[1]), "r"(a[2]), "r"(a[3]), "r"(b0), "r"(b1));
}
#define LDSM4(r0, r1, r2, r3, addr)                                        \
    asm volatile("ldmatrix.sync.aligned.m8n8.x4.shared.b16 {%0,%1,%2,%3}, [%4];" \
                 : "=r"(r0), "=r"(r1), "=r"(r2), "=r"(r3) : "r"(addr))
#define LDSM4T(r0, r1, r2, r3, addr)                                       \
    asm volatile("ldmatrix.sync.aligned.m8n8.x4.trans.shared.b16 {%0,%1,%2,%3}, [%4];" \
                 : "=r"(r0), "=r"(r1), "=r"(r2), "=r"(r3) : "r"(addr))
__device__ __forceinline__ void cp_async16(uint32_t dst, const void* src) {
    asm volatile("cp.async.cg.shared.global [%0], [%1], 16;" :: "r"(dst), "l"(src));
}
__device__ __forceinline__ void cp_commit() { asm volatile("cp.async.commit_group;"); }
template <int N>
__device__ __forceinline__ void cp_wait() {
    asm volatile("cp.async.wait_group %0;" :: "n"(N));
}
__device__ __forceinline__ uint32_t pack_h2(float lo, float hi) {
    __half2 h = __floats2half2_rn(lo, hi);
    return *(uint32_t*)&h;
}

// ---------------------------------------------------------------------------
// Fused prep: one grid does x->fp16 cvt + both weight transposes (independent,
// bandwidth-bound; fusing removes serialization of 3 small launches).
// blocks [0,4096): cvt_x; [4096,7168): w_attn^T; [7168,8192): w_proj^T
// ---------------------------------------------------------------------------
__global__ void __launch_bounds__(256) prep_kernel(const float* __restrict__ x,
                                                   const float* __restrict__ w_attn,
                                                   const float* __restrict__ w_proj) {
    __shared__ float tile[32][33];
    const int blk = blockIdx.x;
    const int tid = threadIdx.x;
    if (blk < 4096) {
        const size_t i = ((size_t)blk * 256 + tid) * 8;
        float4 v0 = *(const float4*)(x + i);
        float4 v1 = *(const float4*)(x + i + 4);
        __half2 h[4];
        h[0] = __floats2half2_rn(v0.x, v0.y);
        h[1] = __floats2half2_rn(v0.z, v0.w);
        h[2] = __floats2half2_rn(v1.x, v1.y);
        h[3] = __floats2half2_rn(v1.z, v1.w);
        *(float4*)(g_x + i) = *(float4*)h;
        return;
    }
    const int tx = tid & 31, ty = tid >> 5;  // 32 x 8
    const float* W;
    __half* WT;
    int n0, k0, ncols;
    if (blk < 4096 + 3072) {
        const int bb = blk - 4096;
        W = w_attn; WT = g_wT; ncols = 3 * Cc;
        n0 = (bb % 96) * 32; k0 = (bb / 96) * 32;
    } else {
        const int bb = blk - 7168;
        W = w_proj; WT = g_wT + (size_t)3 * Cc * Cc; ncols = Cc;
        n0 = (bb % 32) * 32; k0 = (bb / 32) * 32;
    }
#pragma unroll
    for (int r = 0; r < 32; r += 8)
        tile[ty + r][tx] = W[(size_t)(k0 + ty + r) * ncols + n0 + tx];
    __syncthreads();
#pragma unroll
    for (int r = 0; r < 32; r += 8)
        WT[(size_t)(n0 + ty + r) * Cc + k0 + tx] = __float2half_rn(tile[tx][ty + r]);
}

// ---------------------------------------------------------------------------
// fp16 mma GEMM: block tile 128x256, 8 warps (2x4), warp tile 64x64, BK=64,
// 2-stage cp.async (R6 schedule), GST=72 padded rows. 1 CTA/SM (high regs).
// LDSM:MMA ratio 1:4 (vs 3:4 at 64x32 warp tile).
// MODE 1: A = g_x, epilogue scatters fp16 into g_qkv (+bias; Q scaled 0.125)
// MODE 2: A = g_y, epilogue -> Cout fp32 (+bias)
// ---------------------------------------------------------------------------
#define GST 72  // smem row stride in halves
#define A_STG (128 * GST)   // halves per A stage
#define B_STG (256 * GST)   // halves per B stage
template <int MODE>
__global__ void __launch_bounds__(256, 1) mma_gemm(const float* __restrict__ bias,
                                                   float* __restrict__ Cout) {
    extern __shared__ __half smh[];
    __half* As = smh;                 // [2][128*GST]
    __half* Bs = smh + 2 * A_STG;     // [2][256*GST]

    const int tid = threadIdx.x;
    const int lane = tid & 31;
    const int wid = tid >> 5;
    const int g = lane >> 2;
    const int tig = lane & 3;
    const int wm = wid >> 2;   // 0..1 -> 64-row band
    const int wn = wid & 3;    // 0..3 -> 64-col band
    const int row0 = blockIdx.y * 128;
    const int col0 = blockIdx.x * 256;

    const __half* Asrc = (MODE == 2) ? g_y : g_x;
    const __half* Bsrc = (MODE == 2) ? g_wT + (size_t)3 * Cc * Cc : g_wT;

    const uint32_t sA0 = smem_u32(As);
    const uint32_t sB0 = smem_u32(Bs);
    // staging: 16B chunks; A has 1024/stage (4/thread), B has 2048/stage (8/thread)
    const int srow = tid >> 3;           // 0..31 (+32l)
    const int scol = (tid & 7) * 8;      // halves

    float c[4][8][4];
#pragma unroll
    for (int mt = 0; mt < 4; mt++)
#pragma unroll
        for (int nt = 0; nt < 8; nt++)
#pragma unroll
            for (int j = 0; j < 4; j++) c[mt][nt][j] = 0.0f;

    // prologue: stage 0
#pragma unroll
    for (int l = 0; l < 4; l++) {
        const int m = srow + 32 * l;
        cp_async16(sA0 + (m * GST + scol) * 2, Asrc + (size_t)(row0 + m) * Cc + scol);
    }
#pragma unroll
    for (int l = 0; l < 8; l++) {
        const int m = srow + 32 * l;
        cp_async16(sB0 + (m * GST + scol) * 2, Bsrc + (size_t)(col0 + m) * Cc + scol);
    }
    cp_commit();

    // per-warp ldmatrix lane geometry
    const int arow = (lane & 15);
    const int acol = (lane >> 4) * 8;
    const int brow = (lane & 7) + ((lane >> 4) & 1) * 8;
    const int bcol = ((lane >> 3) & 1) * 8;

#pragma unroll 1
    for (int it = 0; it < 16; it++) {  // K = 1024 / 64
        if (it + 1 < 16) {
            const int kb = (it + 1) * 64;
            const uint32_t aoffs = ((it + 1) & 1) * A_STG * 2;
            const uint32_t boffs = ((it + 1) & 1) * B_STG * 2;
#pragma unroll
            for (int l = 0; l < 4; l++) {
                const int m = srow + 32 * l;
                cp_async16(sA0 + aoffs + (m * GST + scol) * 2,
                           Asrc + (size_t)(row0 + m) * Cc + kb + scol);
            }
#pragma unroll
            for (int l = 0; l < 8; l++) {
                const int m = srow + 32 * l;
                cp_async16(sB0 + boffs + (m * GST + scol) * 2,
                           Bsrc + (size_t)(col0 + m) * Cc + kb + scol);
            }
            cp_commit();
            cp_wait<1>();
        } else {
            cp_wait<0>();
        }
        __syncthreads();

        const uint32_t aoff = sA0 + (it & 1) * A_STG * 2;
        const uint32_t boff = sB0 + (it & 1) * B_STG * 2;
#pragma unroll
        for (int ks = 0; ks < 4; ks++) {
            const int k0 = ks * 16;
            uint32_t a[4][4], b[4][4];
#pragma unroll
            for (int mt = 0; mt < 4; mt++) {
                const uint32_t ad =
                    aoff + ((wm * 64 + mt * 16 + arow) * GST + k0 + acol) * 2;
                LDSM4(a[mt][0], a[mt][1], a[mt][2], a[mt][3], ad);
            }
#pragma unroll
            for (int nt2 = 0; nt2 < 4; nt2++) {
                const uint32_t bd =
                    boff + ((wn * 64 + nt2 * 16 + brow) * GST + k0 + bcol) * 2;
                LDSM4(b[nt2][0], b[nt2][1], b[nt2][2], b[nt2][3], bd);
            }
#pragma unroll
            for (int mt = 0; mt < 4; mt++)
#pragma unroll
                for (int nt2 = 0; nt2 < 4; nt2++) {
                    mma16(c[mt][nt2 * 2 + 0], a[mt], b[nt2][0], b[nt2][1]);
                    mma16(c[mt][nt2 * 2 + 1], a[mt], b[nt2][2], b[nt2][3]);
                }
        }
        __syncthreads();
    }

    // Epilogue
#pragma unroll
    for (int nt = 0; nt < 8; nt++) {
        const int n = col0 + wn * 64 + nt * 8 + tig * 2;
        const float b0 = bias[n], b1 = bias[n + 1];
        if (MODE == 2) {
#pragma unroll
            for (int mt = 0; mt < 4; mt++) {
                const int m = row0 + wm * 64 + mt * 16 + g;
                *(float2*)(Cout + (size_t)m * Cc + n) =
                    make_float2(c[mt][nt][0] + b0, c[mt][nt][1] + b1);
                *(float2*)(Cout + (size_t)(m + 8) * Cc + n) =
                    make_float2(c[mt][nt][2] + b0, c[mt][nt][3] + b1);
            }
        } else {
            const int which = n >> 10;
            const int rem = n & 1023;
            const int h = rem >> 6;
            const int d = rem & 63;
            const int bidx = row0 >> 11;
            const int t0 = row0 & 2047;
            const float sc = (which == 0) ? 0.125f : 1.0f;  // fold 1/sqrt(hd) into Q
            __half* base =
                g_qkv + ((((size_t)which * Bc + bidx) * NH + h) * Tc) * HD + d;
#pragma unroll
            for (int mt = 0; mt < 4; mt++) {
                const int r = t0 + wm * 64 + mt * 16 + g;
                *(__half2*)(base + (size_t)r * HD) =
                    __floats2half2_rn((c[mt][nt][0] + b0) * sc, (c[mt][nt][1] + b1) * sc);
                *(__half2*)(base + (size_t)(r + 8) * HD) =
                    __floats2half2_rn((c[mt][nt][2] + b0) * sc, (c[mt][nt][3] + b1) * sc);
            }
        }
    }
}

// ---------------------------------------------------------------------------
// Flash attention (unchanged from R11; measured ~140us component).
// fp16 mma + ldmatrix + cp.async double-buffered K/V, register-resident P.
// ---------------------------------------------------------------------------
#define FST 72
__global__ void __launch_bounds__(256, 2) flash_mma_kernel() {
    extern __shared__ __half fsm[];
    __half* Qs = fsm;                    // [128][FST]
    __half* Ks = Qs + 128 * FST;         // [2][64][FST]
    __half* Vs = Ks + 2 * 64 * FST;      // [2][64][FST]

    const int tid = threadIdx.x;
    const int lane = tid & 31;
    const int w = tid >> 5;
    const int g = lane >> 2;
    const int tig = lane & 3;
    const int band = w * 16;
    const int bh = blockIdx.y;
    const int q0 = blockIdx.x * 128;

    const __half* qb = g_qkv + (size_t)bh * Tc * HD;
    const __half* kb = g_qkv + ((size_t)Bc * NH + bh) * Tc * HD;
    const __half* vb = g_qkv + ((size_t)2 * Bc * NH + bh) * Tc * HD;

    const uint32_t sQ = smem_u32(Qs);
    const uint32_t sK = smem_u32(Ks);
    const uint32_t sV = smem_u32(Vs);

    const int kr1 = tid >> 3, kc1 = (tid & 7) * 8;
    const int kr2 = kr1 + 32;

    // stage Q (synchronous; once)
    {
        const int r0 = tid >> 3, c8 = (tid & 7) * 8;
#pragma unroll
        for (int l = 0; l < 4; l++) {
            const int r = r0 + 32 * l;
            *(float4*)(Qs + r * FST + c8) =
                *(const float4*)(qb + (size_t)(q0 + r) * HD + c8);
        }
    }

    // prologue: cp.async kv tile 0 into buffer 0
    cp_async16(sK + (kr1 * FST + kc1) * 2, kb + (size_t)kr1 * HD + kc1);
    cp_async16(sK + (kr2 * FST + kc1) * 2, kb + (size_t)kr2 * HD + kc1);
    cp_async16(sV + (kr1 * FST + kc1) * 2, vb + (size_t)kr1 * HD + kc1);
    cp_async16(sV + (kr2 * FST + kc1) * 2, vb + (size_t)kr2 * HD + kc1);
    cp_commit();
    __syncthreads();  // Q visible to all warps

    const int arow = (lane & 15);
    const int acol = (lane >> 4) * 8;
    const int brow = (lane & 7) + ((lane >> 4) & 1) * 8;
    const int bcol = ((lane >> 3) & 1) * 8;

    uint32_t qf[4][4];
#pragma unroll
    for (int ks = 0; ks < 4; ks++) {
        const uint32_t ad = sQ + ((band + arow) * FST + ks * 16 + acol) * 2;
        LDSM4(qf[ks][0], qf[ks][1], qf[ks][2], qf[ks][3], ad);
    }

    float o[8][4];
#pragma unroll
    for (int nt = 0; nt < 8; nt++)
#pragma unroll
        for (int j = 0; j < 4; j++) o[nt][j] = 0.0f;
    float m_lo = -1e30f, m_hi = -1e30f, l_lo = 0.0f, l_hi = 0.0f;

    const int row_lo = q0 + band + g;
    const int row_hi = row_lo + 8;
    const int ntiles = 2 * blockIdx.x + 2;

#pragma unroll 1
    for (int kt = 0; kt < ntiles; kt++) {
        const int k0 = kt * 64;
        cp_wait<0>();
        __syncthreads();

        if (kt + 1 < ntiles) {
            const int kn = (kt + 1) * 64;
            const uint32_t off = ((kt + 1) & 1) * 64 * FST * 2;
            cp_async16(sK + off + (kr1 * FST + kc1) * 2, kb + (size_t)(kn + kr1) * HD + kc1);
            cp_async16(sK + off + (kr2 * FST + kc1) * 2, kb + (size_t)(kn + kr2) * HD + kc1);
            cp_async16(sV + off + (kr1 * FST + kc1) * 2, vb + (size_t)(kn + kr1) * HD + kc1);
            cp_async16(sV + off + (kr2 * FST + kc1) * 2, vb + (size_t)(kn + kr2) * HD + kc1);
            cp_commit();
        }

        if (k0 > q0 + band + 15) continue;

        const uint32_t sKb = sK + (kt & 1) * 64 * FST * 2;
        const uint32_t sVb = sV + (kt & 1) * 64 * FST * 2;

        float s[8][4];
#pragma unroll
        for (int nt = 0; nt < 8; nt++)
#pragma unroll
            for (int j = 0; j < 4; j++) s[nt][j] = 0.0f;
#pragma unroll
        for (int ks = 0; ks < 4; ks++) {
#pragma unroll
            for (int nt2 = 0; nt2 < 4; nt2++) {
                uint32_t b[4];
                const uint32_t bd =
                    sKb + ((nt2 * 16 + brow) * FST + ks * 16 + bcol) * 2;
                LDSM4(b[0], b[1], b[2], b[3], bd);
                mma16(s[nt2 * 2 + 0], qf[ks], b[0], b[1]);
                mma16(s[nt2 * 2 + 1], qf[ks], b[2], b[3]);
            }
        }

        const bool diag = (k0 + 63 > q0 + band);
        if (diag) {
#pragma unroll
            for (int nt = 0; nt < 8; nt++) {
                const int cb = k0 + nt * 8 + tig * 2;
                if (cb > row_lo) s[nt][0] = -1e30f;
                if (cb + 1 > row_lo) s[nt][1] = -1e30f;
                if (cb > row_hi) s[nt][2] = -1e30f;
                if (cb + 1 > row_hi) s[nt][3] = -1e30f;
            }
        }

        float mx_lo = -1e30f, mx_hi = -1e30f;
#pragma unroll
        for (int nt = 0; nt < 8; nt++) {
            mx_lo = fmaxf(mx_lo, fmaxf(s[nt][0], s[nt][1]));
            mx_hi = fmaxf(mx_hi, fmaxf(s[nt][2], s[nt][3]));
        }
        mx_lo = fmaxf(mx_lo, __shfl_xor_sync(0xffffffffu, mx_lo, 1));
        mx_lo = fmaxf(mx_lo, __shfl_xor_sync(0xffffffffu, mx_lo, 2));
        mx_hi = fmaxf(mx_hi, __shfl_xor_sync(0xffffffffu, mx_hi, 1));
        mx_hi = fmaxf(mx_hi, __shfl_xor_sync(0xffffffffu, mx_hi, 2));

        const float mn_lo = fmaxf(m_lo, mx_lo);
        const float mn_hi = fmaxf(m_hi, mx_hi);
        const float alpha_lo = __expf(m_lo - mn_lo);
        const float alpha_hi = __expf(m_hi - mn_hi);
        m_lo = mn_lo; m_hi = mn_hi;

        float sum_lo = 0.0f, sum_hi = 0.0f;
#pragma unroll
        for (int nt = 0; nt < 8; nt++) {
            s[nt][0] = __expf(s[nt][0] - mn_lo);
            s[nt][1] = __expf(s[nt][1] - mn_lo);
            s[nt][2] = __expf(s[nt][2] - mn_hi);
            s[nt][3] = __expf(s[nt][3] - mn_hi);
            sum_lo += s[nt][0] + s[nt][1];
            sum_hi += s[nt][2] + s[nt][3];
        }
        sum_lo += __shfl_xor_sync(0xffffffffu, sum_lo, 1);
        sum_lo += __shfl_xor_sync(0xffffffffu, sum_lo, 2);
        sum_hi += __shfl_xor_sync(0xffffffffu, sum_hi, 1);
        sum_hi += __shfl_xor_sync(0xffffffffu, sum_hi, 2);
        l_lo = l_lo * alpha_lo + sum_lo;
        l_hi = l_hi * alpha_hi + sum_hi;

#pragma unroll
        for (int nt = 0; nt < 8; nt++) {
            o[nt][0] *= alpha_lo; o[nt][1] *= alpha_lo;
            o[nt][2] *= alpha_hi; o[nt][3] *= alpha_hi;
        }

#pragma unroll
        for (int ks = 0; ks < 4; ks++) {
            uint32_t a[4];
            a[0] = pack_h2(s[2 * ks][0], s[2 * ks][1]);
            a[1] = pack_h2(s[2 * ks][2], s[2 * ks][3]);
            a[2] = pack_h2(s[2 * ks + 1][0], s[2 * ks + 1][1]);
            a[3] = pack_h2(s[2 * ks + 1][2], s[2 * ks + 1][3]);
#pragma unroll
            for (int nt2 = 0; nt2 < 4; nt2++) {
                uint32_t b[4];
                const uint32_t bd =
                    sVb + ((ks * 16 + arow) * FST + nt2 * 16 + acol) * 2;
                LDSM4T(b[0], b[1], b[2], b[3], bd);
                mma16(o[nt2 * 2 + 0], a, b[0], b[1]);
                mma16(o[nt2 * 2 + 1], a, b[2], b[3]);
            }
        }
    }

    const float inv_lo = 1.0f / l_lo;
    const float inv_hi = 1.0f / l_hi;
    const int b = bh / NH;
    const int h = bh % NH;
    const int t_lo = q0 + band + g;
#pragma unroll
    for (int nt = 0; nt < 8; nt++) {
        const int col = h * HD + nt * 8 + tig * 2;
        *(__half2*)(g_y + ((size_t)b * Tc + t_lo) * Cc + col) =
            __floats2half2_rn(o[nt][0] * inv_lo, o[nt][1] * inv_lo);
        *(__half2*)(g_y + ((size_t)b * Tc + t_lo + 8) * Cc + col) =
            __floats2half2_rn(o[nt][2] * inv_hi, o[nt][3] * inv_hi);
    }
}

// ---------------------------------------------------------------------------
extern "C" void kernel_launch(void* const* d_in, const int* in_sizes, int n_in,
                              void* d_out, int out_size) {
    const float* x = (const float*)d_in[0];
    const float* w_attn = (const float*)d_in[1];
    const float* b_attn = (const float*)d_in[2];
    const float* w_proj = (const float*)d_in[3];
    const float* b_proj = (const float*)d_in[4];
    float* out = (float*)d_out;

    // 0) fused fp16 prep (cvt x + both transposes in one grid)
    prep_kernel<<<8192, 256>>>(x, w_attn, w_proj);

    const int gemm_smem = 2 * (A_STG + B_STG) * 2;  // 110592 B
    cudaFuncSetAttribute(mma_gemm<1>, cudaFuncAttributeMaxDynamicSharedMemorySize, gemm_smem);
    cudaFuncSetAttribute(mma_gemm<2>, cudaFuncAttributeMaxDynamicSharedMemorySize, gemm_smem);

    // 1) QKV = x @ w_attn + b_attn (fp16 mma, 128x256 tile) -> g_qkv
    mma_gemm<1><<<dim3(3 * Cc / 256, Bc * Tc / 128), 256, gemm_smem>>>(b_attn, nullptr);

    // 2) causal flash attention (fp16 mma, register-resident P) -> g_y
    const int fa_smem = (128 + 2 * 64 + 2 * 64) * FST * 2;  // 55296 B
    cudaFuncSetAttribute(flash_mma_kernel,
                         cudaFuncAttributeMaxDynamicSharedMemorySize, fa_smem);
    flash_mma_kernel<<<dim3(Tc / 128, Bc * NH), 256, fa_smem>>>();

    // 3) out = y @ w_proj + b_proj (fp16 mma, 128x256 tile)
    mma_gemm<2><<<dim3(Cc / 256, Bc * Tc / 128), 256, gemm_smem>>>(b_proj, out);
}

// round 13
// speedup vs baseline: 1.1061x; 1.1061x over previous
#include <cuda_runtime.h>
#include <cuda_fp16.h>
#include <cstdint>

#define Bc 4
#define Tc 2048
#define Cc 1024
#define NH 16
#define HD 64

// Scratch (alloc-free rule: __device__ globals). All fp16.
__device__ __half g_x[(size_t)Bc * Tc * Cc];               // fp16 x
__device__ __half g_qkv[(size_t)3 * Bc * NH * Tc * HD];    // [3][B][H][T][HD]; Q pre-scaled by 0.125
__device__ __half g_y[(size_t)Bc * Tc * Cc];               // [B][T][C]
__device__ __half g_wT[(size_t)(3 * Cc + Cc) * Cc];        // w_attn^T then w_proj^T, [N][K]

// ---------------------------------------------------------------------------
// Helpers
// ---------------------------------------------------------------------------
__device__ __forceinline__ uint32_t smem_u32(const void* p) {
    uint32_t a;
    asm("{ .reg .u64 t; cvta.to.shared.u64 t, %1; cvt.u32.u64 %0, t; }"
        : "=r"(a) : "l"(p));
    return a;
}
// m16n8k16 fp16 mma, fp32 accum.
__device__ __forceinline__ void mma16(float* d, const uint32_t* a, uint32_t b0, uint32_t b1) {
    asm volatile(
        "mma.sync.aligned.m16n8k16.row.col.f32.f16.f16.f32 "
        "{%0,%1,%2,%3}, {%4,%5,%6,%7}, {%8,%9}, {%0,%1,%2,%3};"
        : "+f"(d[0]), "+f"(d[1]), "+f"(d[2]), "+f"(d[3])
        : "r"(a[0]), "r"(a[1]), "r"(a[2]), "r"(a[3]), "r"(b0), "r"(b1));
}
#define LDSM4(r0, r1, r2, r3, addr)                                        \
    asm volatile("ldmatrix.sync.aligned.m8n8.x4.shared.b16 {%0,%1,%2,%3}, [%4];" \
                 : "=r"(r0), "=r"(r1), "=r"(r2), "=r"(r3) : "r"(addr))
#define LDSM4T(r0, r1, r2, r3, addr)                                       \
    asm volatile("ldmatrix.sync.aligned.m8n8.x4.trans.shared.b16 {%0,%1,%2,%3}, [%4];" \
                 : "=r"(r0), "=r"(r1), "=r"(r2), "=r"(r3) : "r"(addr))
__device__ __forceinline__ void cp_async16(uint32_t dst, const void* src) {
    asm volatile("cp.async.cg.shared.global [%0], [%1], 16;" :: "r"(dst), "l"(src));
}
__device__ __forceinline__ void cp_commit() { asm volatile("cp.async.commit_group;"); }
template <int N>
__device__ __forceinline__ void cp_wait() {
    asm volatile("cp.async.wait_group %0;" :: "n"(N));
}
__device__ __forceinline__ uint32_t pack_h2(float lo, float hi) {
    __half2 h = __floats2half2_rn(lo, hi);
    return *(uint32_t*)&h;
}

// ---------------------------------------------------------------------------
// Fused prep: one grid does x->fp16 cvt + both weight transposes.
// blocks [0,4096): cvt_x; [4096,7168): w_attn^T; [7168,8192): w_proj^T
// ---------------------------------------------------------------------------
__global__ void __launch_bounds__(256) prep_kernel(const float* __restrict__ x,
                                                   const float* __restrict__ w_attn,
                                                   const float* __restrict__ w_proj) {
    __shared__ float tile[32][33];
    const int blk = blockIdx.x;
    const int tid = threadIdx.x;
    if (blk < 4096) {
        const size_t i = ((size_t)blk * 256 + tid) * 8;
        float4 v0 = *(const float4*)(x + i);
        float4 v1 = *(const float4*)(x + i + 4);
        __half2 h[4];
        h[0] = __floats2half2_rn(v0.x, v0.y);
        h[1] = __floats2half2_rn(v0.z, v0.w);
        h[2] = __floats2half2_rn(v1.x, v1.y);
        h[3] = __floats2half2_rn(v1.z, v1.w);
        *(float4*)(g_x + i) = *(float4*)h;
        return;
    }
    const int tx = tid & 31, ty = tid >> 5;  // 32 x 8
    const float* W;
    __half* WT;
    int n0, k0, ncols;
    if (blk < 4096 + 3072) {
        const int bb = blk - 4096;
        W = w_attn; WT = g_wT; ncols = 3 * Cc;
        n0 = (bb % 96) * 32; k0 = (bb / 96) * 32;
    } else {
        const int bb = blk - 7168;
        W = w_proj; WT = g_wT + (size_t)3 * Cc * Cc; ncols = Cc;
        n0 = (bb % 32) * 32; k0 = (bb / 32) * 32;
    }
#pragma unroll
    for (int r = 0; r < 32; r += 8)
        tile[ty + r][tx] = W[(size_t)(k0 + ty + r) * ncols + n0 + tx];
    __syncthreads();
#pragma unroll
    for (int r = 0; r < 32; r += 8)
        WT[(size_t)(n0 + ty + r) * Cc + k0 + tx] = __float2half_rn(tile[tx][ty + r]);
}

// ---------------------------------------------------------------------------
// fp16 mma GEMM — R11 structure (measured 154us) with ONE sync per K-iter:
// order is wait -> sync -> prefetch -> compute, so the top barrier alone
// protects write-after-read (prefetch for it+1 can only start after every
// warp has finished computing from the buffer it overwrites... which is the
// OTHER buffer; the buffer computed this iter is only overwritten by the
// prefetch issued NEXT iter, after next iter's top sync).
// 256 thr (8 warps), tile 128x128, warp tile 64x32, BK=64, GST=72.
// MODE 1: A = g_x, epilogue scatters fp16 into g_qkv (+bias; Q scaled 0.125)
// MODE 2: A = g_y, epilogue -> Cout fp32 (+bias)
// ---------------------------------------------------------------------------
#define GST 72  // smem row stride in halves
template <int MODE>
__global__ void __launch_bounds__(256, 2) mma_gemm(const float* __restrict__ bias,
                                                   float* __restrict__ Cout) {
    extern __shared__ __half smh[];
    __half* As = smh;                  // [2][128*GST]
    __half* Bs = smh + 2 * 128 * GST;  // [2][128*GST]

    const int tid = threadIdx.x;
    const int lane = tid & 31;
    const int wid = tid >> 5;
    const int g = lane >> 2;
    const int tig = lane & 3;
    const int wm = wid >> 2;   // 0..1 -> 64-row band
    const int wn = wid & 3;    // 0..3 -> 32-col band
    const int row0 = blockIdx.y * 128;
    const int col0 = blockIdx.x * 128;

    const __half* Asrc = (MODE == 2) ? g_y : g_x;
    const __half* Bsrc = (MODE == 2) ? g_wT + (size_t)3 * Cc * Cc : g_wT;

    const uint32_t sA0 = smem_u32(As);
    const uint32_t sB0 = smem_u32(Bs);
    const int srow = tid >> 3;
    const int scol = (tid & 7) * 8;

    float c[4][4][4];
#pragma unroll
    for (int mt = 0; mt < 4; mt++)
#pragma unroll
        for (int nt = 0; nt < 4; nt++)
#pragma unroll
            for (int j = 0; j < 4; j++) c[mt][nt][j] = 0.0f;

    // prologue: stage 0
#pragma unroll
    for (int l = 0; l < 4; l++) {
        const int m = srow + 32 * l;
        cp_async16(sA0 + (m * GST + scol) * 2, Asrc + (size_t)(row0 + m) * Cc + scol);
        cp_async16(sB0 + (m * GST + scol) * 2, Bsrc + (size_t)(col0 + m) * Cc + scol);
    }
    cp_commit();

    // per-warp ldmatrix lane geometry
    const int arow = (lane & 15);
    const int acol = (lane >> 4) * 8;
    const int brow = (lane & 7) + ((lane >> 4) & 1) * 8;
    const int bcol = ((lane >> 3) & 1) * 8;

#pragma unroll 1
    for (int it = 0; it < 16; it++) {  // K = 1024 / 64
        cp_wait<0>();      // stage 'it' arrived (only 1 group in flight)
        __syncthreads();   // + all warps done computing from the buffer that
                           //   this iter's prefetch will overwrite

        if (it + 1 < 16) {
            const int kb = (it + 1) * 64;
            const uint32_t off = ((it + 1) & 1) * 128 * GST * 2;
#pragma unroll
            for (int l = 0; l < 4; l++) {
                const int m = srow + 32 * l;
                cp_async16(sA0 + off + (m * GST + scol) * 2,
                           Asrc + (size_t)(row0 + m) * Cc + kb + scol);
                cp_async16(sB0 + off + (m * GST + scol) * 2,
                           Bsrc + (size_t)(col0 + m) * Cc + kb + scol);
            }
            cp_commit();
        }

        const uint32_t aoff = sA0 + (it & 1) * 128 * GST * 2;
        const uint32_t boff = sB0 + (it & 1) * 128 * GST * 2;
#pragma unroll
        for (int ks = 0; ks < 4; ks++) {
            const int k0 = ks * 16;
            uint32_t a[4][4], b[2][4];
#pragma unroll
            for (int mt = 0; mt < 4; mt++) {
                const uint32_t ad =
                    aoff + ((wm * 64 + mt * 16 + arow) * GST + k0 + acol) * 2;
                LDSM4(a[mt][0], a[mt][1], a[mt][2], a[mt][3], ad);
            }
#pragma unroll
            for (int nt2 = 0; nt2 < 2; nt2++) {
                const uint32_t bd =
                    boff + ((wn * 32 + nt2 * 16 + brow) * GST + k0 + bcol) * 2;
                LDSM4(b[nt2][0], b[nt2][1], b[nt2][2], b[nt2][3], bd);
            }
#pragma unroll
            for (int mt = 0; mt < 4; mt++)
#pragma unroll
                for (int nt2 = 0; nt2 < 2; nt2++) {
                    mma16(c[mt][nt2 * 2 + 0], a[mt], b[nt2][0], b[nt2][1]);
                    mma16(c[mt][nt2 * 2 + 1], a[mt], b[nt2][2], b[nt2][3]);
                }
        }
    }

    // Epilogue
#pragma unroll
    for (int nt = 0; nt < 4; nt++) {
        const int n = col0 + wn * 32 + nt * 8 + tig * 2;
        const float b0 = bias[n], b1 = bias[n + 1];
        if (MODE == 2) {
#pragma unroll
            for (int mt = 0; mt < 4; mt++) {
                const int m = row0 + wm * 64 + mt * 16 + g;
                *(float2*)(Cout + (size_t)m * Cc + n) =
                    make_float2(c[mt][nt][0] + b0, c[mt][nt][1] + b1);
                *(float2*)(Cout + (size_t)(m + 8) * Cc + n) =
                    make_float2(c[mt][nt][2] + b0, c[mt][nt][3] + b1);
            }
        } else {
            const int which = n >> 10;
            const int rem = n & 1023;
            const int h = rem >> 6;
            const int d = rem & 63;
            const int bidx = row0 >> 11;
            const int t0 = row0 & 2047;
            const float sc = (which == 0) ? 0.125f : 1.0f;  // fold 1/sqrt(hd) into Q
            __half* base =
                g_qkv + ((((size_t)which * Bc + bidx) * NH + h) * Tc) * HD + d;
#pragma unroll
            for (int mt = 0; mt < 4; mt++) {
                const int r = t0 + wm * 64 + mt * 16 + g;
                *(__half2*)(base + (size_t)r * HD) =
                    __floats2half2_rn((c[mt][nt][0] + b0) * sc, (c[mt][nt][1] + b1) * sc);
                *(__half2*)(base + (size_t)(r + 8) * HD) =
                    __floats2half2_rn((c[mt][nt][2] + b0) * sc, (c[mt][nt][3] + b1) * sc);
            }
        }
    }
}

// ---------------------------------------------------------------------------
// Flash attention (unchanged from R11 — measured component of the 375us run).
// fp16 mma + ldmatrix + cp.async double-buffered K/V, register-resident P.
// ---------------------------------------------------------------------------
#define FST 72
__global__ void __launch_bounds__(256, 2) flash_mma_kernel() {
    extern __shared__ __half fsm[];
    __half* Qs = fsm;                    // [128][FST]
    __half* Ks = Qs + 128 * FST;         // [2][64][FST]
    __half* Vs = Ks + 2 * 64 * FST;      // [2][64][FST]

    const int tid = threadIdx.x;
    const int lane = tid & 31;
    const int w = tid >> 5;
    const int g = lane >> 2;
    const int tig = lane & 3;
    const int band = w * 16;
    const int bh = blockIdx.y;
    const int q0 = blockIdx.x * 128;

    const __half* qb = g_qkv + (size_t)bh * Tc * HD;
    const __half* kb = g_qkv + ((size_t)Bc * NH + bh) * Tc * HD;
    const __half* vb = g_qkv + ((size_t)2 * Bc * NH + bh) * Tc * HD;

    const uint32_t sQ = smem_u32(Qs);
    const uint32_t sK = smem_u32(Ks);
    const uint32_t sV = smem_u32(Vs);

    const int kr1 = tid >> 3, kc1 = (tid & 7) * 8;
    const int kr2 = kr1 + 32;

    // stage Q (synchronous; once)
    {
        const int r0 = tid >> 3, c8 = (tid & 7) * 8;
#pragma unroll
        for (int l = 0; l < 4; l++) {
            const int r = r0 + 32 * l;
            *(float4*)(Qs + r * FST + c8) =
                *(const float4*)(qb + (size_t)(q0 + r) * HD + c8);
        }
    }

    // prologue: cp.async kv tile 0 into buffer 0
    cp_async16(sK + (kr1 * FST + kc1) * 2, kb + (size_t)kr1 * HD + kc1);
    cp_async16(sK + (kr2 * FST + kc1) * 2, kb + (size_t)kr2 * HD + kc1);
    cp_async16(sV + (kr1 * FST + kc1) * 2, vb + (size_t)kr1 * HD + kc1);
    cp_async16(sV + (kr2 * FST + kc1) * 2, vb + (size_t)kr2 * HD + kc1);
    cp_commit();
    __syncthreads();  // Q visible to all warps

    const int arow = (lane & 15);
    const int acol = (lane >> 4) * 8;
    const int brow = (lane & 7) + ((lane >> 4) & 1) * 8;
    const int bcol = ((lane >> 3) & 1) * 8;

    uint32_t qf[4][4];
#pragma unroll
    for (int ks = 0; ks < 4; ks++) {
        const uint32_t ad = sQ + ((band + arow) * FST + ks * 16 + acol) * 2;
        LDSM4(qf[ks][0], qf[ks][1], qf[ks][2], qf[ks][3], ad);
    }

    float o[8][4];
#pragma unroll
    for (int nt = 0; nt < 8; nt++)
#pragma unroll
        for (int j = 0; j < 4; j++) o[nt][j] = 0.0f;
    float m_lo = -1e30f, m_hi = -1e30f, l_lo = 0.0f, l_hi = 0.0f;

    const int row_lo = q0 + band + g;
    const int row_hi = row_lo + 8;
    const int ntiles = 2 * blockIdx.x + 2;

#pragma unroll 1
    for (int kt = 0; kt < ntiles; kt++) {
        const int k0 = kt * 64;
        cp_wait<0>();
        __syncthreads();

        if (kt + 1 < ntiles) {
            const int kn = (kt + 1) * 64;
            const uint32_t off = ((kt + 1) & 1) * 64 * FST * 2;
            cp_async16(sK + off + (kr1 * FST + kc1) * 2, kb + (size_t)(kn + kr1) * HD + kc1);
            cp_async16(sK + off + (kr2 * FST + kc1) * 2, kb + (size_t)(kn + kr2) * HD + kc1);
            cp_async16(sV + off + (kr1 * FST + kc1) * 2, vb + (size_t)(kn + kr1) * HD + kc1);
            cp_async16(sV + off + (kr2 * FST + kc1) * 2, vb + (size_t)(kn + kr2) * HD + kc1);
            cp_commit();
        }

        if (k0 > q0 + band + 15) continue;

        const uint32_t sKb = sK + (kt & 1) * 64 * FST * 2;
        const uint32_t sVb = sV + (kt & 1) * 64 * FST * 2;

        float s[8][4];
#pragma unroll
        for (int nt = 0; nt < 8; nt++)
#pragma unroll
            for (int j = 0; j < 4; j++) s[nt][j] = 0.0f;
#pragma unroll
        for (int ks = 0; ks < 4; ks++) {
#pragma unroll
            for (int nt2 = 0; nt2 < 4; nt2++) {
                uint32_t b[4];
                const uint32_t bd =
                    sKb + ((nt2 * 16 + brow) * FST + ks * 16 + bcol) * 2;
                LDSM4(b[0], b[1], b[2], b[3], bd);
                mma16(s[nt2 * 2 + 0], qf[ks], b[0], b[1]);
                mma16(s[nt2 * 2 + 1], qf[ks], b[2], b[3]);
            }
        }

        const bool diag = (k0 + 63 > q0 + band);
        if (diag) {
#pragma unroll
            for (int nt = 0; nt < 8; nt++) {
                const int cb = k0 + nt * 8 + tig * 2;
                if (cb > row_lo) s[nt][0] = -1e30f;
                if (cb + 1 > row_lo) s[nt][1] = -1e30f;
                if (cb > row_hi) s[nt][2] = -1e30f;
                if (cb + 1 > row_hi) s[nt][3] = -1e30f;
            }
        }

        float mx_lo = -1e30f, mx_hi = -1e30f;
#pragma unroll
        for (int nt = 0; nt < 8; nt++) {
            mx_lo = fmaxf(mx_lo, fmaxf(s[nt][0], s[nt][1]));
            mx_hi = fmaxf(mx_hi, fmaxf(s[nt][2], s[nt][3]));
        }
        mx_lo = fmaxf(mx_lo, __shfl_xor_sync(0xffffffffu, mx_lo, 1));
        mx_lo = fmaxf(mx_lo, __shfl_xor_sync(0xffffffffu, mx_lo, 2));
        mx_hi = fmaxf(mx_hi, __shfl_xor_sync(0xffffffffu, mx_hi, 1));
        mx_hi = fmaxf(mx_hi, __shfl_xor_sync(0xffffffffu, mx_hi, 2));

        const float mn_lo = fmaxf(m_lo, mx_lo);
        const float mn_hi = fmaxf(m_hi, mx_hi);
        const float alpha_lo = __expf(m_lo - mn_lo);
        const float alpha_hi = __expf(m_hi - mn_hi);
        m_lo = mn_lo; m_hi = mn_hi;

        float sum_lo = 0.0f, sum_hi = 0.0f;
#pragma unroll
        for (int nt = 0; nt < 8; nt++) {
            s[nt][0] = __expf(s[nt][0] - mn_lo);
            s[nt][1] = __expf(s[nt][1] - mn_lo);
            s[nt][2] = __expf(s[nt][2] - mn_hi);
            s[nt][3] = __expf(s[nt][3] - mn_hi);
            sum_lo += s[nt][0] + s[nt][1];
            sum_hi += s[nt][2] + s[nt][3];
        }
        sum_lo += __shfl_xor_sync(0xffffffffu, sum_lo, 1);
        sum_lo += __shfl_xor_sync(0xffffffffu, sum_lo, 2);
        sum_hi += __shfl_xor_sync(0xffffffffu, sum_hi, 1);
        sum_hi += __shfl_xor_sync(0xffffffffu, sum_hi, 2);
        l_lo = l_lo * alpha_lo + sum_lo;
        l_hi = l_hi * alpha_hi + sum_hi;

#pragma unroll
        for (int nt = 0; nt < 8; nt++) {
            o[nt][0] *= alpha_lo; o[nt][1] *= alpha_lo;
            o[nt][2] *= alpha_hi; o[nt][3] *= alpha_hi;
        }

#pragma unroll
        for (int ks = 0; ks < 4; ks++) {
            uint32_t a[4];
            a[0] = pack_h2(s[2 * ks][0], s[2 * ks][1]);
            a[1] = pack_h2(s[2 * ks][2], s[2 * ks][3]);
            a[2] = pack_h2(s[2 * ks + 1][0], s[2 * ks + 1][1]);
            a[3] = pack_h2(s[2 * ks + 1][2], s[2 * ks + 1][3]);
#pragma unroll
            for (int nt2 = 0; nt2 < 4; nt2++) {
                uint32_t b[4];
                const uint32_t bd =
                    sVb + ((ks * 16 + arow) * FST + nt2 * 16 + acol) * 2;
                LDSM4T(b[0], b[1], b[2], b[3], bd);
                mma16(o[nt2 * 2 + 0], a, b[0], b[1]);
                mma16(o[nt2 * 2 + 1], a, b[2], b[3]);
            }
        }
    }

    const float inv_lo = 1.0f / l_lo;
    const float inv_hi = 1.0f / l_hi;
    const int b = bh / NH;
    const int h = bh % NH;
    const int t_lo = q0 + band + g;
#pragma unroll
    for (int nt = 0; nt < 8; nt++) {
        const int col = h * HD + nt * 8 + tig * 2;
        *(__half2*)(g_y + ((size_t)b * Tc + t_lo) * Cc + col) =
            __floats2half2_rn(o[nt][0] * inv_lo, o[nt][1] * inv_lo);
        *(__half2*)(g_y + ((size_t)b * Tc + t_lo + 8) * Cc + col) =
            __floats2half2_rn(o[nt][2] * inv_hi, o[nt][3] * inv_hi);
    }
}

// ---------------------------------------------------------------------------
extern "C" void kernel_launch(void* const* d_in, const int* in_sizes, int n_in,
                              void* d_out, int out_size) {
    const float* x = (const float*)d_in[0];
    const float* w_attn = (const float*)d_in[1];
    const float* b_attn = (const float*)d_in[2];
    const float* w_proj = (const float*)d_in[3];
    const float* b_proj = (const float*)d_in[4];
    float* out = (float*)d_out;

    // 0) fused fp16 prep (cvt x + both transposes in one grid)
    prep_kernel<<<8192, 256>>>(x, w_attn, w_proj);

    const int gemm_smem = 4 * 128 * GST * 2;  // 73728 B
    cudaFuncSetAttribute(mma_gemm<1>, cudaFuncAttributeMaxDynamicSharedMemorySize, gemm_smem);
    cudaFuncSetAttribute(mma_gemm<2>, cudaFuncAttributeMaxDynamicSharedMemorySize, gemm_smem);

    // 1) QKV = x @ w_attn + b_attn (fp16 mma, single-sync pipeline) -> g_qkv
    mma_gemm<1><<<dim3(3 * Cc / 128, Bc * Tc / 128), 256, gemm_smem>>>(b_attn, nullptr);

    // 2) causal flash attention (fp16 mma, register-resident P) -> g_y
    const int fa_smem = (128 + 2 * 64 + 2 * 64) * FST * 2;  // 55296 B
    cudaFuncSetAttribute(flash_mma_kernel,
                         cudaFuncAttributeMaxDynamicSharedMemorySize, fa_smem);
    flash_mma_kernel<<<dim3(Tc / 128, Bc * NH), 256, fa_smem>>>();

    // 3) out = y @ w_proj + b_proj (fp16 mma, single-sync pipeline)
    mma_gemm<2><<<dim3(Cc / 128, Bc * Tc / 128), 256, gemm_smem>>>(b_proj, out);
}

// round 17
// speedup vs baseline: 1.1116x; 1.0049x over previous
#include <cuda_runtime.h>
#include <cuda_fp16.h>
#include <cstdint>

#define Bc 4
#define Tc 2048
#define Cc 1024
#define NH 16
#define HD 64

// Scratch (alloc-free rule: __device__ globals). All fp16.
__device__ __half g_x[(size_t)Bc * Tc * Cc];               // fp16 x
__device__ __half g_qkv[(size_t)3 * Bc * NH * Tc * HD];    // [3][B][H][T][HD]; Q pre-scaled by 0.125*log2(e)
__device__ __half g_y[(size_t)Bc * Tc * Cc];               // [B][T][C]
__device__ __half g_wT[(size_t)(3 * Cc + Cc) * Cc];        // w_attn^T then w_proj^T, [N][K]

// ---------------------------------------------------------------------------
// Helpers
// ---------------------------------------------------------------------------
__device__ __forceinline__ uint32_t smem_u32(const void* p) {
    uint32_t a;
    asm("{ .reg .u64 t; cvta.to.shared.u64 t, %1; cvt.u32.u64 %0, t; }"
        : "=r"(a) : "l"(p));
    return a;
}
// m16n8k16 fp16 mma, fp32 accum.
__device__ __forceinline__ void mma16(float* d, const uint32_t* a, uint32_t b0, uint32_t b1) {
    asm volatile(
        "mma.sync.aligned.m16n8k16.row.col.f32.f16.f16.f32 "
        "{%0,%1,%2,%3}, {%4,%5,%6,%7}, {%8,%9}, {%0,%1,%2,%3};"
        : "+f"(d[0]), "+f"(d[1]), "+f"(d[2]), "+f"(d[3])
        : "r"(a[0]), "r"(a[1]), "r"(a[2]), "r"(a[3]), "r"(b0), "r"(b1));
}
#define LDSM4(r0, r1, r2, r3, addr)                                        \
    asm volatile("ldmatrix.sync.aligned.m8n8.x4.shared.b16 {%0,%1,%2,%3}, [%4];" \
                 : "=r"(r0), "=r"(r1), "=r"(r2), "=r"(r3) : "r"(addr))
#define LDSM4T(r0, r1, r2, r3, addr)                                       \
    asm volatile("ldmatrix.sync.aligned.m8n8.x4.trans.shared.b16 {%0,%1,%2,%3}, [%4];" \
                 : "=r"(r0), "=r"(r1), "=r"(r2), "=r"(r3) : "r"(addr))
__device__ __forceinline__ void cp_async16(uint32_t dst, const void* src) {
    asm volatile("cp.async.cg.shared.global [%0], [%1], 16;" :: "r"(dst), "l"(src));
}
__device__ __forceinline__ void cp_commit() { asm volatile("cp.async.commit_group;"); }
template <int N>
__device__ __forceinline__ void cp_wait() {
    asm volatile("cp.async.wait_group %0;" :: "n"(N));
}
__device__ __forceinline__ uint32_t pack_h2(float lo, float hi) {
    __half2 h = __floats2half2_rn(lo, hi);
    return *(uint32_t*)&h;
}

// ---------------------------------------------------------------------------
// Fused prep: one grid does x->fp16 cvt + both weight transposes.
// blocks [0,4096): cvt_x; [4096,7168): w_attn^T; [7168,8192): w_proj^T
// ---------------------------------------------------------------------------
__global__ void __launch_bounds__(256) prep_kernel(const float* __restrict__ x,
                                                   const float* __restrict__ w_attn,
                                                   const float* __restrict__ w_proj) {
    __shared__ float tile[32][33];
    const int blk = blockIdx.x;
    const int tid = threadIdx.x;
    if (blk < 4096) {
        const size_t i = ((size_t)blk * 256 + tid) * 8;
        float4 v0 = *(const float4*)(x + i);
        float4 v1 = *(const float4*)(x + i + 4);
        __half2 h[4];
        h[0] = __floats2half2_rn(v0.x, v0.y);
        h[1] = __floats2half2_rn(v0.z, v0.w);
        h[2] = __floats2half2_rn(v1.x, v1.y);
        h[3] = __floats2half2_rn(v1.z, v1.w);
        *(float4*)(g_x + i) = *(float4*)h;
        return;
    }
    const int tx = tid & 31, ty = tid >> 5;  // 32 x 8
    const float* W;
    __half* WT;
    int n0, k0, ncols;
    if (blk < 4096 + 3072) {
        const int bb = blk - 4096;
        W = w_attn; WT = g_wT; ncols = 3 * Cc;
        n0 = (bb % 96) * 32; k0 = (bb / 96) * 32;
    } else {
        const int bb = blk - 7168;
        W = w_proj; WT = g_wT + (size_t)3 * Cc * Cc; ncols = Cc;
        n0 = (bb % 32) * 32; k0 = (bb / 32) * 32;
    }
#pragma unroll
    for (int r = 0; r < 32; r += 8)
        tile[ty + r][tx] = W[(size_t)(k0 + ty + r) * ncols + n0 + tx];
    __syncthreads();
#pragma unroll
    for (int r = 0; r < 32; r += 8)
        WT[(size_t)(n0 + ty + r) * Cc + k0 + tx] = __float2half_rn(tile[tx][ty + r]);
}

// ---------------------------------------------------------------------------
// fp16 mma GEMM — single-sync pipeline (R13, measured). 256 thr, tile 128x128,
// warp tile 64x32, BK=64, GST=72, 2 CTAs/SM.
// MODE 1: A = g_x, epilogue scatters fp16 into g_qkv (+bias; Q scaled
//         0.125*log2e so flash can use exp2)
// MODE 2: A = g_y, epilogue -> Cout fp32 (+bias)
// ---------------------------------------------------------------------------
#define GST 72  // smem row stride in halves
#define QSCALE 0.18033688f  // 0.125 * log2(e)
template <int MODE>
__global__ void __launch_bounds__(256, 2) mma_gemm(const float* __restrict__ bias,
                                                   float* __restrict__ Cout) {
    extern __shared__ __half smh[];
    __half* As = smh;                  // [2][128*GST]
    __half* Bs = smh + 2 * 128 * GST;  // [2][128*GST]

    const int tid = threadIdx.x;
    const int lane = tid & 31;
    const int wid = tid >> 5;
    const int g = lane >> 2;
    const int tig = lane & 3;
    const int wm = wid >> 2;   // 0..1 -> 64-row band
    const int wn = wid & 3;    // 0..3 -> 32-col band
    const int row0 = blockIdx.y * 128;
    const int col0 = blockIdx.x * 128;

    const __half* Asrc = (MODE == 2) ? g_y : g_x;
    const __half* Bsrc = (MODE == 2) ? g_wT + (size_t)3 * Cc * Cc : g_wT;

    const uint32_t sA0 = smem_u32(As);
    const uint32_t sB0 = smem_u32(Bs);
    const int srow = tid >> 3;
    const int scol = (tid & 7) * 8;

    float c[4][4][4];
#pragma unroll
    for (int mt = 0; mt < 4; mt++)
#pragma unroll
        for (int nt = 0; nt < 4; nt++)
#pragma unroll
            for (int j = 0; j < 4; j++) c[mt][nt][j] = 0.0f;

    // prologue: stage 0
#pragma unroll
    for (int l = 0; l < 4; l++) {
        const int m = srow + 32 * l;
        cp_async16(sA0 + (m * GST + scol) * 2, Asrc + (size_t)(row0 + m) * Cc + scol);
        cp_async16(sB0 + (m * GST + scol) * 2, Bsrc + (size_t)(col0 + m) * Cc + scol);
    }
    cp_commit();

    const int arow = (lane & 15);
    const int acol = (lane >> 4) * 8;
    const int brow = (lane & 7) + ((lane >> 4) & 1) * 8;
    const int bcol = ((lane >> 3) & 1) * 8;

#pragma unroll 1
    for (int it = 0; it < 16; it++) {  // K = 1024 / 64
        cp_wait<0>();
        __syncthreads();

        if (it + 1 < 16) {
            const int kb = (it + 1) * 64;
            const uint32_t off = ((it + 1) & 1) * 128 * GST * 2;
#pragma unroll
            for (int l = 0; l < 4; l++) {
                const int m = srow + 32 * l;
                cp_async16(sA0 + off + (m * GST + scol) * 2,
                           Asrc + (size_t)(row0 + m) * Cc + kb + scol);
                cp_async16(sB0 + off + (m * GST + scol) * 2,
                           Bsrc + (size_t)(col0 + m) * Cc + kb + scol);
            }
            cp_commit();
        }

        const uint32_t aoff = sA0 + (it & 1) * 128 * GST * 2;
        const uint32_t boff = sB0 + (it & 1) * 128 * GST * 2;
#pragma unroll
        for (int ks = 0; ks < 4; ks++) {
            const int k0 = ks * 16;
            uint32_t a[4][4], b[2][4];
#pragma unroll
            for (int mt = 0; mt < 4; mt++) {
                const uint32_t ad =
                    aoff + ((wm * 64 + mt * 16 + arow) * GST + k0 + acol) * 2;
                LDSM4(a[mt][0], a[mt][1], a[mt][2], a[mt][3], ad);
            }
#pragma unroll
            for (int nt2 = 0; nt2 < 2; nt2++) {
                const uint32_t bd =
                    boff + ((wn * 32 + nt2 * 16 + brow) * GST + k0 + bcol) * 2;
                LDSM4(b[nt2][0], b[nt2][1], b[nt2][2], b[nt2][3], bd);
            }
#pragma unroll
            for (int mt = 0; mt < 4; mt++)
#pragma unroll
                for (int nt2 = 0; nt2 < 2; nt2++) {
                    mma16(c[mt][nt2 * 2 + 0], a[mt], b[nt2][0], b[nt2][1]);
                    mma16(c[mt][nt2 * 2 + 1], a[mt], b[nt2][2], b[nt2][3]);
                }
        }
    }

    // Epilogue
#pragma unroll
    for (int nt = 0; nt < 4; nt++) {
        const int n = col0 + wn * 32 + nt * 8 + tig * 2;
        const float b0 = bias[n], b1 = bias[n + 1];
        if (MODE == 2) {
#pragma unroll
            for (int mt = 0; mt < 4; mt++) {
                const int m = row0 + wm * 64 + mt * 16 + g;
                *(float2*)(Cout + (size_t)m * Cc + n) =
                    make_float2(c[mt][nt][0] + b0, c[mt][nt][1] + b1);
                *(float2*)(Cout + (size_t)(m + 8) * Cc + n) =
                    make_float2(c[mt][nt][2] + b0, c[mt][nt][3] + b1);
            }
        } else {
            const int which = n >> 10;
            const int rem = n & 1023;
            const int h = rem >> 6;
            const int d = rem & 63;
            const int bidx = row0 >> 11;
            const int t0 = row0 & 2047;
            const float sc = (which == 0) ? QSCALE : 1.0f;  // fold scale*log2e into Q
            __half* base =
                g_qkv + ((((size_t)which * Bc + bidx) * NH + h) * Tc) * HD + d;
#pragma unroll
            for (int mt = 0; mt < 4; mt++) {
                const int r = t0 + wm * 64 + mt * 16 + g;
                *(__half2*)(base + (size_t)r * HD) =
                    __floats2half2_rn((c[mt][nt][0] + b0) * sc, (c[mt][nt][1] + b1) * sc);
                *(__half2*)(base + (size_t)(r + 8) * HD) =
                    __floats2half2_rn((c[mt][nt][2] + b0) * sc, (c[mt][nt][3] + b1) * sc);
            }
        }
    }
}

// ---------------------------------------------------------------------------
// Flash attention — R11/R13 structure, softmax in base-2 (Q carries log2e):
// exp2f = bare MUFU.EX2, no companion FMUL. Math exactly equivalent.
// ---------------------------------------------------------------------------
#define FST 72
__global__ void __launch_bounds__(256, 2) flash_mma_kernel() {
    extern __shared__ __half fsm[];
    __half* Qs = fsm;                    // [128][FST]
    __half* Ks = Qs + 128 * FST;         // [2][64][FST]
    __half* Vs = Ks + 2 * 64 * FST;      // [2][64][FST]

    const int tid = threadIdx.x;
    const int lane = tid & 31;
    const int w = tid >> 5;
    const int g = lane >> 2;
    const int tig = lane & 3;
    const int band = w * 16;
    const int bh = blockIdx.y;
    const int q0 = blockIdx.x * 128;

    const __half* qb = g_qkv + (size_t)bh * Tc * HD;
    const __half* kb = g_qkv + ((size_t)Bc * NH + bh) * Tc * HD;
    const __half* vb = g_qkv + ((size_t)2 * Bc * NH + bh) * Tc * HD;

    const uint32_t sQ = smem_u32(Qs);
    const uint32_t sK = smem_u32(Ks);
    const uint32_t sV = smem_u32(Vs);

    const int kr1 = tid >> 3, kc1 = (tid & 7) * 8;
    const int kr2 = kr1 + 32;

    // stage Q (synchronous; once)
    {
        const int r0 = tid >> 3, c8 = (tid & 7) * 8;
#pragma unroll
        for (int l = 0; l < 4; l++) {
            const int r = r0 + 32 * l;
            *(float4*)(Qs + r * FST + c8) =
                *(const float4*)(qb + (size_t)(q0 + r) * HD + c8);
        }
    }

    // prologue: cp.async kv tile 0 into buffer 0
    cp_async16(sK + (kr1 * FST + kc1) * 2, kb + (size_t)kr1 * HD + kc1);
    cp_async16(sK + (kr2 * FST + kc1) * 2, kb + (size_t)kr2 * HD + kc1);
    cp_async16(sV + (kr1 * FST + kc1) * 2, vb + (size_t)kr1 * HD + kc1);
    cp_async16(sV + (kr2 * FST + kc1) * 2, vb + (size_t)kr2 * HD + kc1);
    cp_commit();
    __syncthreads();  // Q visible to all warps

    const int arow = (lane & 15);
    const int acol = (lane >> 4) * 8;
    const int brow = (lane & 7) + ((lane >> 4) & 1) * 8;
    const int bcol = ((lane >> 3) & 1) * 8;

    uint32_t qf[4][4];
#pragma unroll
    for (int ks = 0; ks < 4; ks++) {
        const uint32_t ad = sQ + ((band + arow) * FST + ks * 16 + acol) * 2;
        LDSM4(qf[ks][0], qf[ks][1], qf[ks][2], qf[ks][3], ad);
    }

    float o[8][4];
#pragma unroll
    for (int nt = 0; nt < 8; nt++)
#pragma unroll
        for (int j = 0; j < 4; j++) o[nt][j] = 0.0f;
    float m_lo = -1e30f, m_hi = -1e30f, l_lo = 0.0f, l_hi = 0.0f;

    const int row_lo = q0 + band + g;
    const int row_hi = row_lo + 8;
    const int ntiles = 2 * blockIdx.x + 2;

#pragma unroll 1
    for (int kt = 0; kt < ntiles; kt++) {
        const int k0 = kt * 64;
        cp_wait<0>();
        __syncthreads();

        if (kt + 1 < ntiles) {
            const int kn = (kt + 1) * 64;
            const uint32_t off = ((kt + 1) & 1) * 64 * FST * 2;
            cp_async16(sK + off + (kr1 * FST + kc1) * 2, kb + (size_t)(kn + kr1) * HD + kc1);
            cp_async16(sK + off + (kr2 * FST + kc1) * 2, kb + (size_t)(kn + kr2) * HD + kc1);
            cp_async16(sV + off + (kr1 * FST + kc1) * 2, vb + (size_t)(kn + kr1) * HD + kc1);
            cp_async16(sV + off + (kr2 * FST + kc1) * 2, vb + (size_t)(kn + kr2) * HD + kc1);
            cp_commit();
        }

        if (k0 > q0 + band + 15) continue;

        const uint32_t sKb = sK + (kt & 1) * 64 * FST * 2;
        const uint32_t sVb = sV + (kt & 1) * 64 * FST * 2;

        // S = Q K^T (Q pre-scaled by 0.125*log2e -> base-2 logits)
        float s[8][4];
#pragma unroll
        for (int nt = 0; nt < 8; nt++)
#pragma unroll
            for (int j = 0; j < 4; j++) s[nt][j] = 0.0f;
#pragma unroll
        for (int ks = 0; ks < 4; ks++) {
#pragma unroll
            for (int nt2 = 0; nt2 < 4; nt2++) {
                uint32_t b[4];
                const uint32_t bd =
                    sKb + ((nt2 * 16 + brow) * FST + ks * 16 + bcol) * 2;
                LDSM4(b[0], b[1], b[2], b[3], bd);
                mma16(s[nt2 * 2 + 0], qf[ks], b[0], b[1]);
                mma16(s[nt2 * 2 + 1], qf[ks], b[2], b[3]);
            }
        }

        const bool diag = (k0 + 63 > q0 + band);
        if (diag) {
#pragma unroll
            for (int nt = 0; nt < 8; nt++) {
                const int cb = k0 + nt * 8 + tig * 2;
                if (cb > row_lo) s[nt][0] = -1e30f;
                if (cb + 1 > row_lo) s[nt][1] = -1e30f;
                if (cb > row_hi) s[nt][2] = -1e30f;
                if (cb + 1 > row_hi) s[nt][3] = -1e30f;
            }
        }

        float mx_lo = -1e30f, mx_hi = -1e30f;
#pragma unroll
        for (int nt = 0; nt < 8; nt++) {
            mx_lo = fmaxf(mx_lo, fmaxf(s[nt][0], s[nt][1]));
            mx_hi = fmaxf(mx_hi, fmaxf(s[nt][2], s[nt][3]));
        }
        mx_lo = fmaxf(mx_lo, __shfl_xor_sync(0xffffffffu, mx_lo, 1));
        mx_lo = fmaxf(mx_lo, __shfl_xor_sync(0xffffffffu, mx_lo, 2));
        mx_hi = fmaxf(mx_hi, __shfl_xor_sync(0xffffffffu, mx_hi, 1));
        mx_hi = fmaxf(mx_hi, __shfl_xor_sync(0xffffffffu, mx_hi, 2));

        const float mn_lo = fmaxf(m_lo, mx_lo);
        const float mn_hi = fmaxf(m_hi, mx_hi);
        const float alpha_lo = exp2f(m_lo - mn_lo);
        const float alpha_hi = exp2f(m_hi - mn_hi);
        m_lo = mn_lo; m_hi = mn_hi;

        float sum_lo = 0.0f, sum_hi = 0.0f;
#pragma unroll
        for (int nt = 0; nt < 8; nt++) {
            s[nt][0] = exp2f(s[nt][0] - mn_lo);
            s[nt][1] = exp2f(s[nt][1] - mn_lo);
            s[nt][2] = exp2f(s[nt][2] - mn_hi);
            s[nt][3] = exp2f(s[nt][3] - mn_hi);
            sum_lo += s[nt][0] + s[nt][1];
            sum_hi += s[nt][2] + s[nt][3];
        }
        sum_lo += __shfl_xor_sync(0xffffffffu, sum_lo, 1);
        sum_lo += __shfl_xor_sync(0xffffffffu, sum_lo, 2);
        sum_hi += __shfl_xor_sync(0xffffffffu, sum_hi, 1);
        sum_hi += __shfl_xor_sync(0xffffffffu, sum_hi, 2);
        l_lo = l_lo * alpha_lo + sum_lo;
        l_hi = l_hi * alpha_hi + sum_hi;

#pragma unroll
        for (int nt = 0; nt < 8; nt++) {
            o[nt][0] *= alpha_lo; o[nt][1] *= alpha_lo;
            o[nt][2] *= alpha_hi; o[nt][3] *= alpha_hi;
        }

        // O += P V — P a-fragments built directly from s registers
#pragma unroll
        for (int ks = 0; ks < 4; ks++) {
            uint32_t a[4];
            a[0] = pack_h2(s[2 * ks][0], s[2 * ks][1]);
            a[1] = pack_h2(s[2 * ks][2], s[2 * ks][3]);
            a[2] = pack_h2(s[2 * ks + 1][0], s[2 * ks + 1][1]);
            a[3] = pack_h2(s[2 * ks + 1][2], s[2 * ks + 1][3]);
#pragma unroll
            for (int nt2 = 0; nt2 < 4; nt2++) {
                uint32_t b[4];
                const uint32_t bd =
                    sVb + ((ks * 16 + arow) * FST + nt2 * 16 + acol) * 2;
                LDSM4T(b[0], b[1], b[2], b[3], bd);
                mma16(o[nt2 * 2 + 0], a, b[0], b[1]);
                mma16(o[nt2 * 2 + 1], a, b[2], b[3]);
            }
        }
    }

    const float inv_lo = 1.0f / l_lo;
    const float inv_hi = 1.0f / l_hi;
    const int b = bh / NH;
    const int h = bh % NH;
    const int t_lo = q0 + band + g;
#pragma unroll
    for (int nt = 0; nt < 8; nt++) {
        const int col = h * HD + nt * 8 + tig * 2;
        *(__half2*)(g_y + ((size_t)b * Tc + t_lo) * Cc + col) =
            __floats2half2_rn(o[nt][0] * inv_lo, o[nt][1] * inv_lo);
        *(__half2*)(g_y + ((size_t)b * Tc + t_lo + 8) * Cc + col) =
            __floats2half2_rn(o[nt][2] * inv_hi, o[nt][3] * inv_hi);
    }
}

// ---------------------------------------------------------------------------
extern "C" void kernel_launch(void* const* d_in, const int* in_sizes, int n_in,
                              void* d_out, int out_size) {
    const float* x = (const float*)d_in[0];
    const float* w_attn = (const float*)d_in[1];
    const float* b_attn = (const float*)d_in[2];
    const float* w_proj = (const float*)d_in[3];
    const float* b_proj = (const float*)d_in[4];
    float* out = (float*)d_out;

    // 0) fused fp16 prep (cvt x + both transposes in one grid)
    prep_kernel<<<8192, 256>>>(x, w_attn, w_proj);

    const int gemm_smem = 4 * 128 * GST * 2;  // 73728 B
    cudaFuncSetAttribute(mma_gemm<1>, cudaFuncAttributeMaxDynamicSharedMemorySize, gemm_smem);
    cudaFuncSetAttribute(mma_gemm<2>, cudaFuncAttributeMaxDynamicSharedMemorySize, gemm_smem);

    // 1) QKV = x @ w_attn + b_attn (fp16 mma, single-sync pipeline) -> g_qkv
    mma_gemm<1><<<dim3(3 * Cc / 128, Bc * Tc / 128), 256, gemm_smem>>>(b_attn, nullptr);

    // 2) causal flash attention (fp16 mma, base-2 softmax) -> g_y
    const int fa_smem = (128 + 2 * 64 + 2 * 64) * FST * 2;  // 55296 B
    cudaFuncSetAttribute(flash_mma_kernel,
                         cudaFuncAttributeMaxDynamicSharedMemorySize, fa_smem);
    flash_mma_kernel<<<dim3(Tc / 128, Bc * NH), 256, fa_smem>>>();

    // 3) out = y @ w_proj + b_proj (fp16 mma, single-sync pipeline)
    mma_gemm<2><<<dim3(Cc / 128, Bc * Tc / 128), 256, gemm_smem>>>(b_proj, out);
}